// round 8
// baseline (speedup 1.0000x reference)
#include <cuda_runtime.h>
#include <cuda_fp16.h>
#include <cstdint>

#define B_ 16
#define N_ 196
#define C_ 768
#define H_ 512
#define O_ 128

// ---------------- device scratch (static, no allocs) ----------------
// A panels: [z][b][row 0..191][k 0..767] fp16 (hi/lo split); rows 192..195 handled by tail
__device__ __align__(256) __half g_Ahi[2u*16*192*768];
__device__ __align__(256) __half g_Alo[2u*16*192*768];
// B panel (W transposed): [z][h 0..511][k 0..767] fp16
__device__ __align__(256) __half g_Bhi[2u*512*768];
// partial column sums: [z][b][mt 4][h 512]  (mt 0..2 = main GEMM, mt 3 = tail rows 192..195)
__device__ float g_part[2*16*4*512];

// ---------------- helpers ----------------
__device__ __forceinline__ uint32_t smem_u32(const void* p) {
    uint32_t a;
    asm("{ .reg .u64 t; cvta.to.shared.u64 t, %1; cvt.u32.u64 %0, t; }" : "=r"(a) : "l"(p));
    return a;
}
__device__ __forceinline__ void cp16(uint32_t dst, const void* src) {
    asm volatile("cp.async.cg.shared.global [%0], [%1], 16;" :: "r"(dst), "l"(src) : "memory");
}
__device__ __forceinline__ void ldsm_x4(uint32_t* r, uint32_t addr) {
    asm volatile("ldmatrix.sync.aligned.m8n8.x4.shared.b16 {%0,%1,%2,%3}, [%4];"
                 : "=r"(r[0]), "=r"(r[1]), "=r"(r[2]), "=r"(r[3]) : "r"(addr));
}
__device__ __forceinline__ void mma_f32acc(float* d, const uint32_t* a, const uint32_t* b) {
    asm volatile("mma.sync.aligned.m16n8k16.row.col.f32.f16.f16.f32 "
                 "{%0,%1,%2,%3}, {%4,%5,%6,%7}, {%8,%9}, {%0,%1,%2,%3};"
                 : "+f"(d[0]), "+f"(d[1]), "+f"(d[2]), "+f"(d[3])
                 : "r"(a[0]), "r"(a[1]), "r"(a[2]), "r"(a[3]), "r"(b[0]), "r"(b[1]));
}
__device__ __forceinline__ uint32_t h2_bits(__half a, __half b) {
    __half2 t = __halves2half2(a, b);
    return *reinterpret_cast<uint32_t*>(&t);
}

// ---------------- pack A: x fp32 -> hi/lo fp16 row-major panels (192 rows) ----------------
__global__ void pack_A(const float* __restrict__ x1, const float* __restrict__ x2) {
    int u = blockIdx.x * blockDim.x + threadIdx.x;   // 589824 total
    int kg = u % 96;  int t = u / 96;
    int row = t % 192; t /= 192;
    int b = t & 15;    t >>= 4;
    int z = t;
    const float* x = z ? x2 : x1;
    const float4* src = reinterpret_cast<const float4*>(x + ((size_t)b * N_ + row) * C_ + kg * 8);
    float4 v0 = src[0], v1 = src[1];
    float f[8] = {v0.x, v0.y, v0.z, v0.w, v1.x, v1.y, v1.z, v1.w};
    uint32_t hi[4], lo[4];
    #pragma unroll
    for (int i = 0; i < 4; i++) {
        __half h0 = __float2half_rn(f[2*i]);
        __half h1 = __float2half_rn(f[2*i+1]);
        hi[i] = h2_bits(h0, h1);
        lo[i] = h2_bits(__float2half_rn(f[2*i]   - __half2float(h0)),
                        __float2half_rn(f[2*i+1] - __half2float(h1)));
    }
    size_t off = ((size_t)(z * 16 + b) * 192 + row) * 768 + kg * 8;
    *reinterpret_cast<uint4*>(g_Ahi + off) = make_uint4(hi[0], hi[1], hi[2], hi[3]);
    *reinterpret_cast<uint4*>(g_Alo + off) = make_uint4(lo[0], lo[1], lo[2], lo[3]);
}

// ---------------- pack B: W [C,H] fp32 -> transposed fp16 [H,C] ----------------
__global__ void pack_B(const float* __restrict__ W1, const float* __restrict__ W2) {
    int kc = blockIdx.x, hb = blockIdx.y, z = blockIdx.z;
    const float* W = z ? W2 : W1;
    __shared__ float ts[64][65];
    int tid = threadIdx.x;
    int c0 = kc * 64, h0 = hb * 64;
    #pragma unroll
    for (int i = 0; i < 16; i++) {
        int idx = tid + i * 256;
        int cl = idx >> 6, hl = idx & 63;
        ts[cl][hl] = W[(size_t)(c0 + cl) * H_ + h0 + hl];
    }
    __syncthreads();
    #pragma unroll
    for (int j = 0; j < 2; j++) {
        int unit = tid + j * 256;
        int row = unit >> 3, kg = unit & 7;
        uint32_t hi[4];
        #pragma unroll
        for (int i = 0; i < 4; i++) {
            hi[i] = h2_bits(__float2half_rn(ts[kg * 8 + 2*i][row]),
                            __float2half_rn(ts[kg * 8 + 2*i + 1][row]));
        }
        size_t off = ((size_t)z * 512 + h0 + row) * 768 + c0 + kg * 8;
        *reinterpret_cast<uint4*>(g_Bhi + off) = make_uint4(hi[0], hi[1], hi[2], hi[3]);
    }
}

// ---------------- GEMM: mma.sync 2-term fp16 split + relu + colsum ----------------
// Main blocks: tile M=64, N=128, BK=64, 256 threads (8 warps: wm{0,1} x wn{0..3},
// warp m32 x n32), 2-stage ping-pong, 3 CTAs/SM. Rows padded to 144B (conflict-free ldsm).
// Tail block (x==12): rows 192..195 fp32 GEMV.
#define ROWB 144
#define A_TERM (64*ROWB)          // 9216
#define B_OFF  (2*A_TERM)         // 18432
#define STAGE_BYTES (B_OFF + 128*ROWB)   // 36864
#define SMEM_TOTAL (2*STAGE_BYTES)       // 73728

__device__ __forceinline__ void load_stage(
    uint32_t base, int kbase, int tid,
    const __half* Ah, const __half* Al, const __half* Bh)
{
    #pragma unroll
    for (int i = 0; i < 4; i++) {                 // A: 1024 16B units (2 terms x 64 rows x 8 q)
        int u = tid + i * 256;
        int term = u & 1, q = (u >> 1) & 7, row = u >> 4;
        const __half* src = (term ? Al : Ah) + (size_t)row * 768 + kbase + q * 8;
        cp16(base + term * A_TERM + row * ROWB + q * 16, src);
    }
    #pragma unroll
    for (int i = 0; i < 4; i++) {                 // B: 1024 16B units (128 rows x 8 q)
        int u = tid + i * 256;
        int q = u & 7, row = u >> 3;
        const __half* src = Bh + (size_t)row * 768 + kbase + q * 8;
        cp16(base + B_OFF + row * ROWB + q * 16, src);
    }
    asm volatile("cp.async.commit_group;" ::: "memory");
}

__global__ __launch_bounds__(256, 3) void gemm_hmma(
    const float* __restrict__ x1, const float* __restrict__ x2,
    const float* __restrict__ W1, const float* __restrict__ W2)
{
    extern __shared__ char sm[];
    uint32_t sb = smem_u32(sm);
    int tid = threadIdx.x, wid = tid >> 5, lane = tid & 31;
    int z = blockIdx.z, b = blockIdx.y;

    if (blockIdx.x == 12) {
        // ---- tail: rows 192..195, fp32 GEMV over original data, all 512 h ----
        const float* x = z ? x2 : x1;
        const float* W = z ? W2 : W1;
        float* xs = (float*)sm;                  // [4][768]
        #pragma unroll
        for (int i = 0; i < 3; i++) {
            int u = tid + i * 256;               // 768 float4 units
            if (u < 768) {
                int r = u / 192, k4 = u % 192;
                *reinterpret_cast<float4*>(xs + r * 768 + k4 * 4) =
                    *reinterpret_cast<const float4*>(x + ((size_t)b * N_ + 192 + r) * C_ + k4 * 4);
            }
        }
        __syncthreads();
        #pragma unroll
        for (int hh = 0; hh < 2; hh++) {
            int h = hh * 256 + tid;
            float d0 = 0.f, d1 = 0.f, d2 = 0.f, d3 = 0.f;
            #pragma unroll 8
            for (int k = 0; k < 768; k++) {
                float w = W[(size_t)k * H_ + h];
                d0 = fmaf(xs[k], w, d0);
                d1 = fmaf(xs[768 + k], w, d1);
                d2 = fmaf(xs[1536 + k], w, d2);
                d3 = fmaf(xs[2304 + k], w, d3);
            }
            g_part[((size_t)(z * 16 + b) * 4 + 3) * 512 + h] =
                fmaxf(d0, 0.f) + fmaxf(d1, 0.f) + fmaxf(d2, 0.f) + fmaxf(d3, 0.f);
        }
        return;
    }

    int mt = blockIdx.x >> 2, nt = blockIdx.x & 3;
    int wm = wid & 1, wn = wid >> 1;
    const __half* Ah = g_Ahi + ((size_t)(z * 16 + b) * 192 + mt * 64) * 768;
    const __half* Al = g_Alo + ((size_t)(z * 16 + b) * 192 + mt * 64) * 768;
    const __half* Bh = g_Bhi + ((size_t)z * 512 + nt * 128) * 768;

    float acc[2][4][4];          // [mf][nf][d], fp32 accum: xh*W + xl*W
    #pragma unroll
    for (int mf = 0; mf < 2; mf++)
        #pragma unroll
        for (int nf = 0; nf < 4; nf++)
            #pragma unroll
            for (int d = 0; d < 4; d++) acc[mf][nf][d] = 0.f;

    uint32_t aoff[2];
    #pragma unroll
    for (int mf = 0; mf < 2; mf++) {
        int row = wm * 32 + mf * 16 + (lane & 7) + ((lane >> 3) & 1) * 8;
        aoff[mf] = row * ROWB + (lane >> 4) * 16;
    }
    uint32_t boff[2];
    #pragma unroll
    for (int np = 0; np < 2; np++) {
        int row = wn * 32 + np * 16 + (lane & 7) + (lane >> 4) * 8;
        boff[np] = row * ROWB + ((lane >> 3) & 1) * 16;
    }

    load_stage(sb, 0, tid, Ah, Al, Bh);

    int buf = 0;
    for (int s = 0; s < 12; s++) {
        if (s + 1 < 12) {
            load_stage(sb + (buf ^ 1) * STAGE_BYTES, (s + 1) * 64, tid, Ah, Al, Bh);
            asm volatile("cp.async.wait_group 1;" ::: "memory");
        } else {
            asm volatile("cp.async.wait_group 0;" ::: "memory");
        }
        __syncthreads();

        uint32_t abase = sb + buf * STAGE_BYTES;
        uint32_t bbase = abase + B_OFF;
        #pragma unroll
        for (int kk = 0; kk < 4; kk++) {
            uint32_t ah[2][4], al[2][4], bh[2][4];
            #pragma unroll
            for (int mf = 0; mf < 2; mf++) {
                ldsm_x4(ah[mf], abase + aoff[mf] + kk * 32);
                ldsm_x4(al[mf], abase + A_TERM + aoff[mf] + kk * 32);
            }
            #pragma unroll
            for (int np = 0; np < 2; np++)
                ldsm_x4(bh[np], bbase + boff[np] + kk * 32);
            #pragma unroll
            for (int mf = 0; mf < 2; mf++)
                #pragma unroll
                for (int nf = 0; nf < 4; nf++) {
                    int np = nf >> 1, hh = (nf & 1) * 2;
                    uint32_t bb[2] = { bh[np][hh], bh[np][hh + 1] };
                    mma_f32acc(acc[mf][nf], ah[mf], bb);   // xh * W
                    mma_f32acc(acc[mf][nf], al[mf], bb);   // xl * W
                }
        }
        __syncthreads();
        buf ^= 1;
    }

    // ---------------- epilogue: relu + column sums ----------------
    float* red = (float*)sm;     // [2][128] floats, reuse smem
    #pragma unroll
    for (int nf = 0; nf < 4; nf++) {
        float s0 = 0.f, s1 = 0.f;
        #pragma unroll
        for (int mf = 0; mf < 2; mf++) {
            s0 += fmaxf(acc[mf][nf][0], 0.f) + fmaxf(acc[mf][nf][2], 0.f);
            s1 += fmaxf(acc[mf][nf][1], 0.f) + fmaxf(acc[mf][nf][3], 0.f);
        }
        #pragma unroll
        for (int off = 4; off < 32; off <<= 1) {
            s0 += __shfl_xor_sync(0xffffffff, s0, off);
            s1 += __shfl_xor_sync(0xffffffff, s1, off);
        }
        if (lane < 4) {
            red[wm * 128 + wn * 32 + nf * 8 + lane * 2]     = s0;
            red[wm * 128 + wn * 32 + nf * 8 + lane * 2 + 1] = s1;
        }
    }
    __syncthreads();
    if (tid < 128) {
        float part = red[tid] + red[128 + tid];
        g_part[((size_t)(z * 16 + b) * 4 + mt) * 512 + nt * 128 + tid] = part;
    }
}

// ---------------- finalize ----------------
__global__ void init_out(const float* __restrict__ bp, float* __restrict__ out) {
    int b = blockIdx.x, o = threadIdx.x;
    out[b * O_ + o] = bp[o] * 38416.f;
}

__global__ void finalize_acc(const float* __restrict__ Wp, float* __restrict__ out) {
    int b = blockIdx.x, hc = blockIdx.y;   // hc in 0..3, 128 h each
    int tid = threadIdx.x;                 // 128
    __shared__ float sp[128];
    {
        int h = hc * 128 + tid;
        float c1 = 0.f, c2 = 0.f;
        #pragma unroll
        for (int mtq = 0; mtq < 4; mtq++) {
            c1 += g_part[((size_t)(0 * 16 + b) * 4 + mtq) * 512 + h];
            c2 += g_part[((size_t)(1 * 16 + b) * 4 + mtq) * 512 + h];
        }
        sp[tid] = c1 * c2;
    }
    __syncthreads();
    float acc = 0.f;
    #pragma unroll 16
    for (int i = 0; i < 128; i++)
        acc = fmaf(sp[i], Wp[(size_t)(hc * 128 + i) * O_ + tid], acc);
    atomicAdd(&out[b * O_ + tid], acc);
}

// ---------------- launch ----------------
extern "C" void kernel_launch(void* const* d_in, const int* in_sizes, int n_in,
                              void* d_out, int out_size) {
    const float* x1 = (const float*)d_in[0];
    const float* x2 = (const float*)d_in[1];
    const float* W1 = (const float*)d_in[2];
    const float* W2 = (const float*)d_in[3];
    const float* Wp = (const float*)d_in[4];
    const float* bp = (const float*)d_in[5];
    float* out = (float*)d_out;

    cudaFuncSetAttribute(gemm_hmma, cudaFuncAttributeMaxDynamicSharedMemorySize, SMEM_TOTAL);

    init_out<<<16, 128>>>(bp, out);
    pack_A<<<2304, 256>>>(x1, x2);
    pack_B<<<dim3(12, 8, 2), 256>>>(W1, W2);
    gemm_hmma<<<dim3(13, 16, 2), 256, SMEM_TOTAL>>>(x1, x2, W1, W2);
    finalize_acc<<<dim3(16, 4), 128>>>(Wp, out);
}

// round 9
// speedup vs baseline: 1.0801x; 1.0801x over previous
#include <cuda_runtime.h>
#include <cuda_fp16.h>
#include <cstdint>

#define B_ 16
#define N_ 196
#define C_ 768
#define H_ 512
#define O_ 128

// ---------------- device scratch (static, no allocs) ----------------
// A panel: [z][b][row 0..191][k 0..767] fp16; rows 192..195 handled by tail blocks
__device__ __align__(256) __half g_A[2u*16*192*768];
// B panel (W transposed): [z][h 0..511][k 0..767] fp16
__device__ __align__(256) __half g_B[2u*512*768];
// partial column sums: [z][b][mt 4][h 512]  (mt 0..2 = main GEMM, mt 3 = tail rows 192..195)
__device__ float g_part[2*16*4*512];

// ---------------- helpers ----------------
__device__ __forceinline__ uint32_t smem_u32(const void* p) {
    uint32_t a;
    asm("{ .reg .u64 t; cvta.to.shared.u64 t, %1; cvt.u32.u64 %0, t; }" : "=r"(a) : "l"(p));
    return a;
}
__device__ __forceinline__ void cp16(uint32_t dst, const void* src) {
    asm volatile("cp.async.cg.shared.global [%0], [%1], 16;" :: "r"(dst), "l"(src) : "memory");
}
__device__ __forceinline__ void ldsm_x4(uint32_t* r, uint32_t addr) {
    asm volatile("ldmatrix.sync.aligned.m8n8.x4.shared.b16 {%0,%1,%2,%3}, [%4];"
                 : "=r"(r[0]), "=r"(r[1]), "=r"(r[2]), "=r"(r[3]) : "r"(addr));
}
__device__ __forceinline__ void mma_f32acc(float* d, const uint32_t* a, const uint32_t* b) {
    asm volatile("mma.sync.aligned.m16n8k16.row.col.f32.f16.f16.f32 "
                 "{%0,%1,%2,%3}, {%4,%5,%6,%7}, {%8,%9}, {%0,%1,%2,%3};"
                 : "+f"(d[0]), "+f"(d[1]), "+f"(d[2]), "+f"(d[3])
                 : "r"(a[0]), "r"(a[1]), "r"(a[2]), "r"(a[3]), "r"(b[0]), "r"(b[1]));
}
__device__ __forceinline__ uint32_t h2_bits(__half a, __half b) {
    __half2 t = __halves2half2(a, b);
    return *reinterpret_cast<uint32_t*>(&t);
}

// ---------------- pack A: x fp32 -> fp16 row-major panel (192 rows) ----------------
__global__ void pack_A(const float* __restrict__ x1, const float* __restrict__ x2) {
    int u = blockIdx.x * blockDim.x + threadIdx.x;   // 589824 total
    int kg = u % 96;  int t = u / 96;
    int row = t % 192; t /= 192;
    int b = t & 15;    t >>= 4;
    int z = t;
    const float* x = z ? x2 : x1;
    const float4* src = reinterpret_cast<const float4*>(x + ((size_t)b * N_ + row) * C_ + kg * 8);
    float4 v0 = src[0], v1 = src[1];
    uint32_t hi[4];
    hi[0] = h2_bits(__float2half_rn(v0.x), __float2half_rn(v0.y));
    hi[1] = h2_bits(__float2half_rn(v0.z), __float2half_rn(v0.w));
    hi[2] = h2_bits(__float2half_rn(v1.x), __float2half_rn(v1.y));
    hi[3] = h2_bits(__float2half_rn(v1.z), __float2half_rn(v1.w));
    size_t off = ((size_t)(z * 16 + b) * 192 + row) * 768 + kg * 8;
    *reinterpret_cast<uint4*>(g_A + off) = make_uint4(hi[0], hi[1], hi[2], hi[3]);
}

// ---------------- pack B: W [C,H] fp32 -> transposed fp16 [H,C] ----------------
__global__ void pack_B(const float* __restrict__ W1, const float* __restrict__ W2) {
    int kc = blockIdx.x, hb = blockIdx.y, z = blockIdx.z;
    const float* W = z ? W2 : W1;
    __shared__ float ts[64][65];
    int tid = threadIdx.x;
    int c0 = kc * 64, h0 = hb * 64;
    #pragma unroll
    for (int i = 0; i < 16; i++) {
        int idx = tid + i * 256;
        int cl = idx >> 6, hl = idx & 63;
        ts[cl][hl] = W[(size_t)(c0 + cl) * H_ + h0 + hl];
    }
    __syncthreads();
    #pragma unroll
    for (int j = 0; j < 2; j++) {
        int unit = tid + j * 256;
        int row = unit >> 3, kg = unit & 7;
        uint32_t hi[4];
        #pragma unroll
        for (int i = 0; i < 4; i++) {
            hi[i] = h2_bits(__float2half_rn(ts[kg * 8 + 2*i][row]),
                            __float2half_rn(ts[kg * 8 + 2*i + 1][row]));
        }
        size_t off = ((size_t)z * 512 + h0 + row) * 768 + c0 + kg * 8;
        *reinterpret_cast<uint4*>(g_B + off) = make_uint4(hi[0], hi[1], hi[2], hi[3]);
    }
}

// ---------------- GEMM: single-term fp16 mma.sync + relu + colsum ----------------
// Main blocks: tile M=64, N=256, BK=32, 256 threads (8 warps: wm{0,1} x wn{0..3},
// warp m32 x n64). 3-stage circular buffer, ONE __syncthreads per stage, 2 CTAs/SM.
// Tail block (x==6): rows 192..195 fp32 GEMV.
#define ROWB 80
#define B_OFF 5120                        // A: 64 rows x 80B
#define STAGE_BYTES (B_OFF + 256*ROWB)    // 25600
#define SMEM_TOTAL (3*STAGE_BYTES)        // 76800

__device__ __forceinline__ void load_stage(
    uint32_t base, int kbase, int tid, const __half* A, const __half* Bp)
{
    {   // A: 256 16B units (64 rows x 4 quads)
        int q = tid & 3, row = tid >> 2;
        cp16(base + row * ROWB + q * 16, A + (size_t)row * 768 + kbase + q * 8);
    }
    #pragma unroll
    for (int i = 0; i < 4; i++) {                 // B: 1024 16B units (256 rows x 4 quads)
        int u = tid + i * 256;
        int q = u & 3, row = u >> 2;
        cp16(base + B_OFF + row * ROWB + q * 16, Bp + (size_t)row * 768 + kbase + q * 8);
    }
    asm volatile("cp.async.commit_group;" ::: "memory");
}

__global__ __launch_bounds__(256, 2) void gemm_hmma(
    const float* __restrict__ x1, const float* __restrict__ x2,
    const float* __restrict__ W1, const float* __restrict__ W2)
{
    extern __shared__ char sm[];
    uint32_t sb = smem_u32(sm);
    int tid = threadIdx.x, wid = tid >> 5, lane = tid & 31;
    int z = blockIdx.z, b = blockIdx.y;

    if (blockIdx.x == 6) {
        // ---- tail: rows 192..195, fp32 GEMV over original data, all 512 h ----
        const float* x = z ? x2 : x1;
        const float* W = z ? W2 : W1;
        float* xs = (float*)sm;                  // [4][768]
        #pragma unroll
        for (int i = 0; i < 3; i++) {
            int u = tid + i * 256;               // 768 float4 units
            if (u < 768) {
                int r = u / 192, k4 = u % 192;
                *reinterpret_cast<float4*>(xs + r * 768 + k4 * 4) =
                    *reinterpret_cast<const float4*>(x + ((size_t)b * N_ + 192 + r) * C_ + k4 * 4);
            }
        }
        __syncthreads();
        #pragma unroll
        for (int hh = 0; hh < 2; hh++) {
            int h = hh * 256 + tid;
            float d0 = 0.f, d1 = 0.f, d2 = 0.f, d3 = 0.f;
            #pragma unroll 8
            for (int k = 0; k < 768; k++) {
                float w = W[(size_t)k * H_ + h];
                d0 = fmaf(xs[k], w, d0);
                d1 = fmaf(xs[768 + k], w, d1);
                d2 = fmaf(xs[1536 + k], w, d2);
                d3 = fmaf(xs[2304 + k], w, d3);
            }
            g_part[((size_t)(z * 16 + b) * 4 + 3) * 512 + h] =
                fmaxf(d0, 0.f) + fmaxf(d1, 0.f) + fmaxf(d2, 0.f) + fmaxf(d3, 0.f);
        }
        return;
    }

    int mt = blockIdx.x >> 1, nt = blockIdx.x & 1;
    int wm = wid & 1, wn = wid >> 1;
    const __half* A  = g_A + ((size_t)(z * 16 + b) * 192 + mt * 64) * 768;
    const __half* Bp = g_B + ((size_t)z * 512 + nt * 256) * 768;

    float acc[2][8][4];
    #pragma unroll
    for (int mf = 0; mf < 2; mf++)
        #pragma unroll
        for (int nf = 0; nf < 8; nf++)
            #pragma unroll
            for (int d = 0; d < 4; d++) acc[mf][nf][d] = 0.f;

    uint32_t aoff[2];
    #pragma unroll
    for (int mf = 0; mf < 2; mf++) {
        int row = wm * 32 + mf * 16 + (lane & 7) + ((lane >> 3) & 1) * 8;
        aoff[mf] = row * ROWB + (lane >> 4) * 16;
    }
    uint32_t boff[4];
    #pragma unroll
    for (int np = 0; np < 4; np++) {
        int row = wn * 64 + np * 16 + (lane & 7) + (lane >> 4) * 8;
        boff[np] = row * ROWB + ((lane >> 3) & 1) * 16;
    }

    load_stage(sb, 0, tid, A, Bp);
    load_stage(sb + STAGE_BYTES, 32, tid, A, Bp);

    int buf = 0;
    for (int s = 0; s < 24; s++) {
        if (s + 2 < 24) {
            asm volatile("cp.async.wait_group 1;" ::: "memory");
        } else {
            asm volatile("cp.async.wait_group 0;" ::: "memory");
        }
        __syncthreads();
        // issue next loads AFTER the barrier: the target buffer (buf+2)%3 was
        // consumed in iteration s-1, and the barrier guarantees all warps passed it.
        if (s + 2 < 24) {
            int nb = buf + 2; if (nb >= 3) nb -= 3;
            load_stage(sb + nb * STAGE_BYTES, (s + 2) * 32, tid, A, Bp);
        }

        uint32_t abase = sb + buf * STAGE_BYTES;
        uint32_t bbase = abase + B_OFF;
        #pragma unroll
        for (int kk = 0; kk < 2; kk++) {
            uint32_t ah[2][4], bh[4][4];
            #pragma unroll
            for (int mf = 0; mf < 2; mf++)
                ldsm_x4(ah[mf], abase + aoff[mf] + kk * 32);
            #pragma unroll
            for (int np = 0; np < 4; np++)
                ldsm_x4(bh[np], bbase + boff[np] + kk * 32);
            #pragma unroll
            for (int mf = 0; mf < 2; mf++)
                #pragma unroll
                for (int nf = 0; nf < 8; nf++) {
                    int np = nf >> 1, hh = (nf & 1) * 2;
                    uint32_t bb[2] = { bh[np][hh], bh[np][hh + 1] };
                    mma_f32acc(acc[mf][nf], ah[mf], bb);
                }
        }
        if (++buf == 3) buf = 0;
    }
    __syncthreads();   // protect smem reuse by epilogue

    // ---------------- epilogue: relu + column sums ----------------
    float* red = (float*)sm;     // [2][256] floats, reuse smem
    #pragma unroll
    for (int nf = 0; nf < 8; nf++) {
        float s0 = 0.f, s1 = 0.f;
        #pragma unroll
        for (int mf = 0; mf < 2; mf++) {
            s0 += fmaxf(acc[mf][nf][0], 0.f) + fmaxf(acc[mf][nf][2], 0.f);
            s1 += fmaxf(acc[mf][nf][1], 0.f) + fmaxf(acc[mf][nf][3], 0.f);
        }
        #pragma unroll
        for (int off = 4; off < 32; off <<= 1) {
            s0 += __shfl_xor_sync(0xffffffff, s0, off);
            s1 += __shfl_xor_sync(0xffffffff, s1, off);
        }
        if (lane < 4) {
            red[wm * 256 + wn * 64 + nf * 8 + lane * 2]     = s0;
            red[wm * 256 + wn * 64 + nf * 8 + lane * 2 + 1] = s1;
        }
    }
    __syncthreads();
    float part = red[tid] + red[256 + tid];
    g_part[((size_t)(z * 16 + b) * 4 + mt) * 512 + nt * 256 + tid] = part;
}

// ---------------- finalize ----------------
__global__ void init_out(const float* __restrict__ bp, float* __restrict__ out) {
    int b = blockIdx.x, o = threadIdx.x;
    out[b * O_ + o] = bp[o] * 38416.f;
}

__global__ void finalize_acc(const float* __restrict__ Wp, float* __restrict__ out) {
    int b = blockIdx.x, hc = blockIdx.y;   // hc in 0..3, 128 h each
    int tid = threadIdx.x;                 // 128
    __shared__ float sp[128];
    {
        int h = hc * 128 + tid;
        float c1 = 0.f, c2 = 0.f;
        #pragma unroll
        for (int mtq = 0; mtq < 4; mtq++) {
            c1 += g_part[((size_t)(0 * 16 + b) * 4 + mtq) * 512 + h];
            c2 += g_part[((size_t)(1 * 16 + b) * 4 + mtq) * 512 + h];
        }
        sp[tid] = c1 * c2;
    }
    __syncthreads();
    float acc = 0.f;
    #pragma unroll 16
    for (int i = 0; i < 128; i++)
        acc = fmaf(sp[i], Wp[(size_t)(hc * 128 + i) * O_ + tid], acc);
    atomicAdd(&out[b * O_ + tid], acc);
}

// ---------------- launch ----------------
extern "C" void kernel_launch(void* const* d_in, const int* in_sizes, int n_in,
                              void* d_out, int out_size) {
    const float* x1 = (const float*)d_in[0];
    const float* x2 = (const float*)d_in[1];
    const float* W1 = (const float*)d_in[2];
    const float* W2 = (const float*)d_in[3];
    const float* Wp = (const float*)d_in[4];
    const float* bp = (const float*)d_in[5];
    float* out = (float*)d_out;

    cudaFuncSetAttribute(gemm_hmma, cudaFuncAttributeMaxDynamicSharedMemorySize, SMEM_TOTAL);

    init_out<<<16, 128>>>(bp, out);
    pack_A<<<2304, 256>>>(x1, x2);
    pack_B<<<dim3(12, 8, 2), 256>>>(W1, W2);
    gemm_hmma<<<dim3(7, 16, 2), 256, SMEM_TOTAL>>>(x1, x2, W1, W2);
    finalize_acc<<<dim3(16, 4), 128>>>(Wp, out);
}

// round 10
// speedup vs baseline: 1.4697x; 1.3607x over previous
#include <cuda_runtime.h>
#include <cuda_fp16.h>
#include <cstdint>

#define B_ 16
#define N_ 196
#define C_ 768
#define H_ 512
#define O_ 128

// ---------------- device scratch (static, no allocs) ----------------
// A panel: [z][b][row 0..255][k 0..767] fp16, rows >= 196 zero (padding is benign: relu(0)=0)
__device__ __align__(256) __half g_A[2u*16*256*768];
// B panel (W transposed): [z][h 0..511][k 0..767] fp16
__device__ __align__(256) __half g_B[2u*512*768];
// partial column sums: [z][b][mt 4][h 512]
__device__ float g_part[2*16*4*512];

// ---------------- helpers ----------------
__device__ __forceinline__ uint32_t smem_u32(const void* p) {
    uint32_t a;
    asm("{ .reg .u64 t; cvta.to.shared.u64 t, %1; cvt.u32.u64 %0, t; }" : "=r"(a) : "l"(p));
    return a;
}
__device__ __forceinline__ void cp16(uint32_t dst, const void* src) {
    asm volatile("cp.async.cg.shared.global [%0], [%1], 16;" :: "r"(dst), "l"(src) : "memory");
}
__device__ __forceinline__ void ldsm_x4(uint32_t* r, uint32_t addr) {
    asm volatile("ldmatrix.sync.aligned.m8n8.x4.shared.b16 {%0,%1,%2,%3}, [%4];"
                 : "=r"(r[0]), "=r"(r[1]), "=r"(r[2]), "=r"(r[3]) : "r"(addr));
}
__device__ __forceinline__ void mma_f32acc(float* d, const uint32_t* a, const uint32_t* b) {
    asm volatile("mma.sync.aligned.m16n8k16.row.col.f32.f16.f16.f32 "
                 "{%0,%1,%2,%3}, {%4,%5,%6,%7}, {%8,%9}, {%0,%1,%2,%3};"
                 : "+f"(d[0]), "+f"(d[1]), "+f"(d[2]), "+f"(d[3])
                 : "r"(a[0]), "r"(a[1]), "r"(a[2]), "r"(a[3]), "r"(b[0]), "r"(b[1]));
}
__device__ __forceinline__ uint32_t h2_bits(__half a, __half b) {
    __half2 t = __halves2half2(a, b);
    return *reinterpret_cast<uint32_t*>(&t);
}

// ---------------- pack A: x fp32 -> fp16 row-major panel (256 rows, zero padded) ----------------
__global__ void pack_A(const float* __restrict__ x1, const float* __restrict__ x2) {
    int u = blockIdx.x * blockDim.x + threadIdx.x;   // 786432 total
    int kg = u % 96;  int t = u / 96;
    int row = t & 255; t >>= 8;
    int b = t & 15;    t >>= 4;
    int z = t;
    const float* x = z ? x2 : x1;
    uint32_t hv[4];
    if (row < N_) {
        const float4* src = reinterpret_cast<const float4*>(x + ((size_t)b * N_ + row) * C_ + kg * 8);
        float4 v0 = src[0], v1 = src[1];
        hv[0] = h2_bits(__float2half_rn(v0.x), __float2half_rn(v0.y));
        hv[1] = h2_bits(__float2half_rn(v0.z), __float2half_rn(v0.w));
        hv[2] = h2_bits(__float2half_rn(v1.x), __float2half_rn(v1.y));
        hv[3] = h2_bits(__float2half_rn(v1.z), __float2half_rn(v1.w));
    } else {
        hv[0] = hv[1] = hv[2] = hv[3] = 0u;
    }
    size_t off = ((size_t)(z * 16 + b) * 256 + row) * 768 + kg * 8;
    *reinterpret_cast<uint4*>(g_A + off) = make_uint4(hv[0], hv[1], hv[2], hv[3]);
}

// ---------------- pack B: W [C,H] fp32 -> transposed fp16 [H,C] ----------------
__global__ void pack_B(const float* __restrict__ W1, const float* __restrict__ W2) {
    int kc = blockIdx.x, hb = blockIdx.y, z = blockIdx.z;
    const float* W = z ? W2 : W1;
    __shared__ float ts[64][65];
    int tid = threadIdx.x;
    int c0 = kc * 64, h0 = hb * 64;
    #pragma unroll
    for (int i = 0; i < 16; i++) {
        int idx = tid + i * 256;
        int cl = idx >> 6, hl = idx & 63;
        ts[cl][hl] = W[(size_t)(c0 + cl) * H_ + h0 + hl];
    }
    __syncthreads();
    #pragma unroll
    for (int j = 0; j < 2; j++) {
        int unit = tid + j * 256;
        int row = unit >> 3, kg = unit & 7;
        uint32_t hi[4];
        #pragma unroll
        for (int i = 0; i < 4; i++) {
            hi[i] = h2_bits(__float2half_rn(ts[kg * 8 + 2*i][row]),
                            __float2half_rn(ts[kg * 8 + 2*i + 1][row]));
        }
        size_t off = ((size_t)z * 512 + h0 + row) * 768 + c0 + kg * 8;
        *reinterpret_cast<uint4*>(g_B + off) = make_uint4(hi[0], hi[1], hi[2], hi[3]);
    }
}

// ---------------- GEMM: single-term fp16 mma.sync + relu + colsum ----------------
// Tile M=64, N=256, BK=32, 256 threads (8 warps: wm{0,1} x wn{0..3}, warp m32 x n64).
// 2-stage ping-pong, R7-proven loop structure, 2 CTAs/SM, 256 CTAs = single wave.
#define ROWB 80
#define B_OFF 5120                        // A: 64 rows x 80B
#define STAGE_BYTES (B_OFF + 256*ROWB)    // 25600
#define SMEM_TOTAL (2*STAGE_BYTES)        // 51200

__device__ __forceinline__ void load_stage(
    uint32_t base, int kbase, int tid, const __half* A, const __half* Bp)
{
    {   // A: 256 16B units (64 rows x 4 quads)
        int q = tid & 3, row = tid >> 2;
        cp16(base + row * ROWB + q * 16, A + (size_t)row * 768 + kbase + q * 8);
    }
    #pragma unroll
    for (int i = 0; i < 4; i++) {                 // B: 1024 16B units (256 rows x 4 quads)
        int u = tid + i * 256;
        int q = u & 3, row = u >> 2;
        cp16(base + B_OFF + row * ROWB + q * 16, Bp + (size_t)row * 768 + kbase + q * 8);
    }
    asm volatile("cp.async.commit_group;" ::: "memory");
}

__global__ __launch_bounds__(256, 2) void gemm_hmma()
{
    extern __shared__ char sm[];
    uint32_t sb = smem_u32(sm);
    int tid = threadIdx.x, wid = tid >> 5, lane = tid & 31;
    int z = blockIdx.z, b = blockIdx.y;
    int mt = blockIdx.x >> 1, nt = blockIdx.x & 1;
    int wm = wid & 1, wn = wid >> 1;

    const __half* A  = g_A + ((size_t)(z * 16 + b) * 256 + mt * 64) * 768;
    const __half* Bp = g_B + ((size_t)z * 512 + nt * 256) * 768;

    float acc[2][8][4];
    #pragma unroll
    for (int mf = 0; mf < 2; mf++)
        #pragma unroll
        for (int nf = 0; nf < 8; nf++)
            #pragma unroll
            for (int d = 0; d < 4; d++) acc[mf][nf][d] = 0.f;

    uint32_t aoff[2];
    #pragma unroll
    for (int mf = 0; mf < 2; mf++) {
        int row = wm * 32 + mf * 16 + (lane & 7) + ((lane >> 3) & 1) * 8;
        aoff[mf] = row * ROWB + (lane >> 4) * 16;
    }
    uint32_t boff[4];
    #pragma unroll
    for (int np = 0; np < 4; np++) {
        int row = wn * 64 + np * 16 + (lane & 7) + (lane >> 4) * 8;
        boff[np] = row * ROWB + ((lane >> 3) & 1) * 16;
    }

    load_stage(sb, 0, tid, A, Bp);

    for (int s = 0; s < 24; s++) {
        if (s < 23) {
            load_stage(sb + ((s + 1) & 1) * STAGE_BYTES, (s + 1) * 32, tid, A, Bp);
            asm volatile("cp.async.wait_group 1;" ::: "memory");
        } else {
            asm volatile("cp.async.wait_group 0;" ::: "memory");
        }
        __syncthreads();

        uint32_t abase = sb + (s & 1) * STAGE_BYTES;
        uint32_t bbase = abase + B_OFF;
        #pragma unroll
        for (int kk = 0; kk < 2; kk++) {
            uint32_t ah[2][4], bh[4][4];
            #pragma unroll
            for (int mf = 0; mf < 2; mf++)
                ldsm_x4(ah[mf], abase + aoff[mf] + kk * 32);
            #pragma unroll
            for (int np = 0; np < 4; np++)
                ldsm_x4(bh[np], bbase + boff[np] + kk * 32);
            #pragma unroll
            for (int mf = 0; mf < 2; mf++)
                #pragma unroll
                for (int nf = 0; nf < 8; nf++) {
                    int np = nf >> 1, hh = (nf & 1) * 2;
                    uint32_t bb[2] = { bh[np][hh], bh[np][hh + 1] };
                    mma_f32acc(acc[mf][nf], ah[mf], bb);
                }
        }
        __syncthreads();
    }

    // ---------------- epilogue: relu + column sums ----------------
    float* red = (float*)sm;     // [2][256] floats, reuse smem
    #pragma unroll
    for (int nf = 0; nf < 8; nf++) {
        float s0 = 0.f, s1 = 0.f;
        #pragma unroll
        for (int mf = 0; mf < 2; mf++) {
            s0 += fmaxf(acc[mf][nf][0], 0.f) + fmaxf(acc[mf][nf][2], 0.f);
            s1 += fmaxf(acc[mf][nf][1], 0.f) + fmaxf(acc[mf][nf][3], 0.f);
        }
        #pragma unroll
        for (int off = 4; off < 32; off <<= 1) {
            s0 += __shfl_xor_sync(0xffffffff, s0, off);
            s1 += __shfl_xor_sync(0xffffffff, s1, off);
        }
        if (lane < 4) {
            red[wm * 256 + wn * 64 + nf * 8 + lane * 2]     = s0;
            red[wm * 256 + wn * 64 + nf * 8 + lane * 2 + 1] = s1;
        }
    }
    __syncthreads();
    float part = red[tid] + red[256 + tid];
    g_part[((size_t)(z * 16 + b) * 4 + mt) * 512 + nt * 256 + tid] = part;
}

// ---------------- finalize ----------------
__global__ void init_out(const float* __restrict__ bp, float* __restrict__ out) {
    int b = blockIdx.x, o = threadIdx.x;
    out[b * O_ + o] = bp[o] * 38416.f;
}

__global__ void finalize_acc(const float* __restrict__ Wp, float* __restrict__ out) {
    int b = blockIdx.x, hc = blockIdx.y;   // hc in 0..3, 128 h each
    int tid = threadIdx.x;                 // 128
    __shared__ float sp[128];
    {
        int h = hc * 128 + tid;
        float c1 = 0.f, c2 = 0.f;
        #pragma unroll
        for (int mtq = 0; mtq < 4; mtq++) {
            c1 += g_part[((size_t)(0 * 16 + b) * 4 + mtq) * 512 + h];
            c2 += g_part[((size_t)(1 * 16 + b) * 4 + mtq) * 512 + h];
        }
        sp[tid] = c1 * c2;
    }
    __syncthreads();
    float acc = 0.f;
    #pragma unroll 16
    for (int i = 0; i < 128; i++)
        acc = fmaf(sp[i], Wp[(size_t)(hc * 128 + i) * O_ + tid], acc);
    atomicAdd(&out[b * O_ + tid], acc);
}

// ---------------- launch ----------------
extern "C" void kernel_launch(void* const* d_in, const int* in_sizes, int n_in,
                              void* d_out, int out_size) {
    const float* x1 = (const float*)d_in[0];
    const float* x2 = (const float*)d_in[1];
    const float* W1 = (const float*)d_in[2];
    const float* W2 = (const float*)d_in[3];
    const float* Wp = (const float*)d_in[4];
    const float* bp = (const float*)d_in[5];
    float* out = (float*)d_out;

    cudaFuncSetAttribute(gemm_hmma, cudaFuncAttributeMaxDynamicSharedMemorySize, SMEM_TOTAL);

    init_out<<<16, 128>>>(bp, out);
    pack_A<<<3072, 256>>>(x1, x2);
    pack_B<<<dim3(12, 8, 2), 256>>>(W1, W2);
    gemm_hmma<<<dim3(8, 16, 2), 256, SMEM_TOTAL>>>();
    finalize_acc<<<dim3(16, 4), 128>>>(Wp, out);
}

// round 11
// speedup vs baseline: 1.6064x; 1.0930x over previous
#include <cuda_runtime.h>
#include <cuda_fp16.h>
#include <cstdint>

#define B_ 16
#define N_ 196
#define C_ 768
#define H_ 512
#define O_ 128

// ---------------- device scratch (static, no allocs) ----------------
// A panel: [z][b][row 0..255][k 0..767] fp16, rows >= 196 zero (padding benign: relu(0)=0)
__device__ __align__(256) __half g_A[2u*16*256*768];
// B panel (W transposed): [z][h 0..511][k 0..767] fp16
__device__ __align__(256) __half g_B[2u*512*768];
// partial column sums: [z][b][mt 4][h 512]
__device__ float g_part[2*16*4*512];

// ---------------- helpers ----------------
__device__ __forceinline__ uint32_t smem_u32(const void* p) {
    uint32_t a;
    asm("{ .reg .u64 t; cvta.to.shared.u64 t, %1; cvt.u32.u64 %0, t; }" : "=r"(a) : "l"(p));
    return a;
}
__device__ __forceinline__ void cp16(uint32_t dst, const void* src) {
    asm volatile("cp.async.cg.shared.global [%0], [%1], 16;" :: "r"(dst), "l"(src) : "memory");
}
__device__ __forceinline__ void ldsm_x4(uint32_t* r, uint32_t addr) {
    asm volatile("ldmatrix.sync.aligned.m8n8.x4.shared.b16 {%0,%1,%2,%3}, [%4];"
                 : "=r"(r[0]), "=r"(r[1]), "=r"(r[2]), "=r"(r[3]) : "r"(addr));
}
__device__ __forceinline__ void mma_f32acc(float* d, const uint32_t* a, const uint32_t* b) {
    asm volatile("mma.sync.aligned.m16n8k16.row.col.f32.f16.f16.f32 "
                 "{%0,%1,%2,%3}, {%4,%5,%6,%7}, {%8,%9}, {%0,%1,%2,%3};"
                 : "+f"(d[0]), "+f"(d[1]), "+f"(d[2]), "+f"(d[3])
                 : "r"(a[0]), "r"(a[1]), "r"(a[2]), "r"(a[3]), "r"(b[0]), "r"(b[1]));
}
__device__ __forceinline__ uint32_t h2_bits(__half a, __half b) {
    __half2 t = __halves2half2(a, b);
    return *reinterpret_cast<uint32_t*>(&t);
}

// ---------------- pack A: x fp32 -> fp16 row-major panel (256 rows, zero padded) ----------------
__global__ void pack_A(const float* __restrict__ x1, const float* __restrict__ x2) {
    int u = blockIdx.x * blockDim.x + threadIdx.x;   // 786432 total
    int kg = u % 96;  int t = u / 96;
    int row = t & 255; t >>= 8;
    int b = t & 15;    t >>= 4;
    int z = t;
    const float* x = z ? x2 : x1;
    uint32_t hv[4];
    if (row < N_) {
        const float4* src = reinterpret_cast<const float4*>(x + ((size_t)b * N_ + row) * C_ + kg * 8);
        float4 v0 = src[0], v1 = src[1];
        hv[0] = h2_bits(__float2half_rn(v0.x), __float2half_rn(v0.y));
        hv[1] = h2_bits(__float2half_rn(v0.z), __float2half_rn(v0.w));
        hv[2] = h2_bits(__float2half_rn(v1.x), __float2half_rn(v1.y));
        hv[3] = h2_bits(__float2half_rn(v1.z), __float2half_rn(v1.w));
    } else {
        hv[0] = hv[1] = hv[2] = hv[3] = 0u;
    }
    size_t off = ((size_t)(z * 16 + b) * 256 + row) * 768 + kg * 8;
    *reinterpret_cast<uint4*>(g_A + off) = make_uint4(hv[0], hv[1], hv[2], hv[3]);
}

// ---------------- pack B: W [C,H] fp32 -> transposed fp16 [H,C] ----------------
__global__ void pack_B(const float* __restrict__ W1, const float* __restrict__ W2) {
    int kc = blockIdx.x, hb = blockIdx.y, z = blockIdx.z;
    const float* W = z ? W2 : W1;
    __shared__ float ts[64][65];
    int tid = threadIdx.x;
    int c0 = kc * 64, h0 = hb * 64;
    #pragma unroll
    for (int i = 0; i < 16; i++) {
        int idx = tid + i * 256;
        int cl = idx >> 6, hl = idx & 63;
        ts[cl][hl] = W[(size_t)(c0 + cl) * H_ + h0 + hl];
    }
    __syncthreads();
    #pragma unroll
    for (int j = 0; j < 2; j++) {
        int unit = tid + j * 256;
        int row = unit >> 3, kg = unit & 7;
        uint32_t hi[4];
        #pragma unroll
        for (int i = 0; i < 4; i++) {
            hi[i] = h2_bits(__float2half_rn(ts[kg * 8 + 2*i][row]),
                            __float2half_rn(ts[kg * 8 + 2*i + 1][row]));
        }
        size_t off = ((size_t)z * 512 + h0 + row) * 768 + c0 + kg * 8;
        *reinterpret_cast<uint4*>(g_B + off) = make_uint4(hi[0], hi[1], hi[2], hi[3]);
    }
}

// ---------------- GEMM: single-term fp16 mma.sync + relu + colsum ----------------
// Tile M=64, N=256, BK=64, 256 threads (8 warps: wm{0,1} x wn{0..3}, warp m32 x n64).
// 2-stage ping-pong, load-before-wait, 12 K-stages, 2 CTAs/SM, 256 CTAs = single wave.
#define ROWB 144
#define B_OFF (64*ROWB)                   // A: 64 rows x 144B = 9216
#define STAGE_BYTES (B_OFF + 256*ROWB)    // 46080
#define SMEM_TOTAL (2*STAGE_BYTES)        // 92160

__device__ __forceinline__ void load_stage(
    uint32_t base, int kbase, int tid, const __half* A, const __half* Bp)
{
    #pragma unroll
    for (int i = 0; i < 2; i++) {                 // A: 512 16B units (64 rows x 8 quads)
        int u = tid + i * 256;
        int q = u & 7, row = u >> 3;
        cp16(base + row * ROWB + q * 16, A + (size_t)row * 768 + kbase + q * 8);
    }
    #pragma unroll
    for (int i = 0; i < 8; i++) {                 // B: 2048 16B units (256 rows x 8 quads)
        int u = tid + i * 256;
        int q = u & 7, row = u >> 3;
        cp16(base + B_OFF + row * ROWB + q * 16, Bp + (size_t)row * 768 + kbase + q * 8);
    }
    asm volatile("cp.async.commit_group;" ::: "memory");
}

__global__ __launch_bounds__(256, 2) void gemm_hmma()
{
    extern __shared__ char sm[];
    uint32_t sb = smem_u32(sm);
    int tid = threadIdx.x, wid = tid >> 5, lane = tid & 31;
    int z = blockIdx.z, b = blockIdx.y;
    int mt = blockIdx.x >> 1, nt = blockIdx.x & 1;
    int wm = wid & 1, wn = wid >> 1;

    const __half* A  = g_A + ((size_t)(z * 16 + b) * 256 + mt * 64) * 768;
    const __half* Bp = g_B + ((size_t)z * 512 + nt * 256) * 768;

    float acc[2][8][4];
    #pragma unroll
    for (int mf = 0; mf < 2; mf++)
        #pragma unroll
        for (int nf = 0; nf < 8; nf++)
            #pragma unroll
            for (int d = 0; d < 4; d++) acc[mf][nf][d] = 0.f;

    uint32_t aoff[2];
    #pragma unroll
    for (int mf = 0; mf < 2; mf++) {
        int row = wm * 32 + mf * 16 + (lane & 7) + ((lane >> 3) & 1) * 8;
        aoff[mf] = row * ROWB + (lane >> 4) * 16;
    }
    uint32_t boff[4];
    #pragma unroll
    for (int np = 0; np < 4; np++) {
        int row = wn * 64 + np * 16 + (lane & 7) + (lane >> 4) * 8;
        boff[np] = row * ROWB + ((lane >> 3) & 1) * 16;
    }

    load_stage(sb, 0, tid, A, Bp);

    for (int s = 0; s < 12; s++) {
        if (s < 11) {
            load_stage(sb + ((s + 1) & 1) * STAGE_BYTES, (s + 1) * 64, tid, A, Bp);
            asm volatile("cp.async.wait_group 1;" ::: "memory");
        } else {
            asm volatile("cp.async.wait_group 0;" ::: "memory");
        }
        __syncthreads();

        uint32_t abase = sb + (s & 1) * STAGE_BYTES;
        uint32_t bbase = abase + B_OFF;
        #pragma unroll
        for (int kk = 0; kk < 4; kk++) {
            uint32_t ah[2][4], bh[4][4];
            #pragma unroll
            for (int mf = 0; mf < 2; mf++)
                ldsm_x4(ah[mf], abase + aoff[mf] + kk * 32);
            #pragma unroll
            for (int np = 0; np < 4; np++)
                ldsm_x4(bh[np], bbase + boff[np] + kk * 32);
            #pragma unroll
            for (int mf = 0; mf < 2; mf++)
                #pragma unroll
                for (int nf = 0; nf < 8; nf++) {
                    int np = nf >> 1, hh = (nf & 1) * 2;
                    uint32_t bb[2] = { bh[np][hh], bh[np][hh + 1] };
                    mma_f32acc(acc[mf][nf], ah[mf], bb);
                }
        }
        __syncthreads();
    }

    // ---------------- epilogue: relu + column sums ----------------
    float* red = (float*)sm;     // [2][256] floats, reuse smem
    #pragma unroll
    for (int nf = 0; nf < 8; nf++) {
        float s0 = 0.f, s1 = 0.f;
        #pragma unroll
        for (int mf = 0; mf < 2; mf++) {
            s0 += fmaxf(acc[mf][nf][0], 0.f) + fmaxf(acc[mf][nf][2], 0.f);
            s1 += fmaxf(acc[mf][nf][1], 0.f) + fmaxf(acc[mf][nf][3], 0.f);
        }
        #pragma unroll
        for (int off = 4; off < 32; off <<= 1) {
            s0 += __shfl_xor_sync(0xffffffff, s0, off);
            s1 += __shfl_xor_sync(0xffffffff, s1, off);
        }
        if (lane < 4) {
            red[wm * 256 + wn * 64 + nf * 8 + lane * 2]     = s0;
            red[wm * 256 + wn * 64 + nf * 8 + lane * 2 + 1] = s1;
        }
    }
    __syncthreads();
    float part = red[tid] + red[256 + tid];
    g_part[((size_t)(z * 16 + b) * 4 + mt) * 512 + nt * 256 + tid] = part;
}

// ---------------- finalize ----------------
__global__ void init_out(const float* __restrict__ bp, float* __restrict__ out) {
    int b = blockIdx.x, o = threadIdx.x;
    out[b * O_ + o] = bp[o] * 38416.f;
}

__global__ void finalize_acc(const float* __restrict__ Wp, float* __restrict__ out) {
    int b = blockIdx.x, hc = blockIdx.y;   // hc in 0..3, 128 h each
    int tid = threadIdx.x;                 // 128
    __shared__ float sp[128];
    {
        int h = hc * 128 + tid;
        float c1 = 0.f, c2 = 0.f;
        #pragma unroll
        for (int mtq = 0; mtq < 4; mtq++) {
            c1 += g_part[((size_t)(0 * 16 + b) * 4 + mtq) * 512 + h];
            c2 += g_part[((size_t)(1 * 16 + b) * 4 + mtq) * 512 + h];
        }
        sp[tid] = c1 * c2;
    }
    __syncthreads();
    float acc = 0.f;
    #pragma unroll 16
    for (int i = 0; i < 128; i++)
        acc = fmaf(sp[i], Wp[(size_t)(hc * 128 + i) * O_ + tid], acc);
    atomicAdd(&out[b * O_ + tid], acc);
}

// ---------------- launch ----------------
extern "C" void kernel_launch(void* const* d_in, const int* in_sizes, int n_in,
                              void* d_out, int out_size) {
    const float* x1 = (const float*)d_in[0];
    const float* x2 = (const float*)d_in[1];
    const float* W1 = (const float*)d_in[2];
    const float* W2 = (const float*)d_in[3];
    const float* Wp = (const float*)d_in[4];
    const float* bp = (const float*)d_in[5];
    float* out = (float*)d_out;

    cudaFuncSetAttribute(gemm_hmma, cudaFuncAttributeMaxDynamicSharedMemorySize, SMEM_TOTAL);

    init_out<<<16, 128>>>(bp, out);
    pack_A<<<3072, 256>>>(x1, x2);
    pack_B<<<dim3(12, 8, 2), 256>>>(W1, W2);
    gemm_hmma<<<dim3(8, 16, 2), 256, SMEM_TOTAL>>>();
    finalize_acc<<<dim3(16, 4), 128>>>(Wp, out);
}

// round 12
// speedup vs baseline: 1.7363x; 1.0809x over previous
#include <cuda_runtime.h>
#include <cuda_fp16.h>
#include <cstdint>

#define B_ 16
#define N_ 196
#define C_ 768
#define H_ 512
#define O_ 128

// ---------------- device scratch (static, no allocs) ----------------
// A panel: [z][b][row 0..255][k 0..767] fp16, rows >= 196 zero (padding benign: relu(0)=0)
__device__ __align__(256) __half g_A[2u*16*256*768];
// B panel (W transposed): [z][h 0..511][k 0..767] fp16
__device__ __align__(256) __half g_B[2u*512*768];
// partial column sums: [z][b][mt 4][h 512]
__device__ float g_part[2*16*4*512];

// ---------------- helpers ----------------
__device__ __forceinline__ uint32_t smem_u32(const void* p) {
    uint32_t a;
    asm("{ .reg .u64 t; cvta.to.shared.u64 t, %1; cvt.u32.u64 %0, t; }" : "=r"(a) : "l"(p));
    return a;
}
__device__ __forceinline__ void cp16(uint32_t dst, const void* src) {
    asm volatile("cp.async.cg.shared.global [%0], [%1], 16;" :: "r"(dst), "l"(src) : "memory");
}
__device__ __forceinline__ void ldsm_x4(uint32_t* r, uint32_t addr) {
    asm volatile("ldmatrix.sync.aligned.m8n8.x4.shared.b16 {%0,%1,%2,%3}, [%4];"
                 : "=r"(r[0]), "=r"(r[1]), "=r"(r[2]), "=r"(r[3]) : "r"(addr));
}
__device__ __forceinline__ void mma_f32acc(float* d, const uint32_t* a, const uint32_t* b) {
    asm volatile("mma.sync.aligned.m16n8k16.row.col.f32.f16.f16.f32 "
                 "{%0,%1,%2,%3}, {%4,%5,%6,%7}, {%8,%9}, {%0,%1,%2,%3};"
                 : "+f"(d[0]), "+f"(d[1]), "+f"(d[2]), "+f"(d[3])
                 : "r"(a[0]), "r"(a[1]), "r"(a[2]), "r"(a[3]), "r"(b[0]), "r"(b[1]));
}
__device__ __forceinline__ uint32_t h2_bits(__half a, __half b) {
    __half2 t = __halves2half2(a, b);
    return *reinterpret_cast<uint32_t*>(&t);
}

// ---------------- fused pack: A panel + B panel + out-bias init, one launch ----------------
// blocks [0,3072): pack_A ; [3072,3264): pack_B ; 3264: init out with bias
__global__ void pack_all(const float* __restrict__ x1, const float* __restrict__ x2,
                         const float* __restrict__ W1, const float* __restrict__ W2,
                         const float* __restrict__ bp, float* __restrict__ out)
{
    __shared__ float ts[64][65];
    int bx = blockIdx.x;
    int tid = threadIdx.x;

    if (bx < 3072) {
        // ---- pack A: x fp32 -> fp16 panel (256 rows, zero padded) ----
        int u = bx * 256 + tid;
        int kg = u % 96;  int t = u / 96;
        int row = t & 255; t >>= 8;
        int b = t & 15;    t >>= 4;
        int z = t;
        const float* x = z ? x2 : x1;
        uint32_t hv[4];
        if (row < N_) {
            const float4* src = reinterpret_cast<const float4*>(x + ((size_t)b * N_ + row) * C_ + kg * 8);
            float4 v0 = src[0], v1 = src[1];
            hv[0] = h2_bits(__float2half_rn(v0.x), __float2half_rn(v0.y));
            hv[1] = h2_bits(__float2half_rn(v0.z), __float2half_rn(v0.w));
            hv[2] = h2_bits(__float2half_rn(v1.x), __float2half_rn(v1.y));
            hv[3] = h2_bits(__float2half_rn(v1.z), __float2half_rn(v1.w));
        } else {
            hv[0] = hv[1] = hv[2] = hv[3] = 0u;
        }
        size_t off = ((size_t)(z * 16 + b) * 256 + row) * 768 + kg * 8;
        *reinterpret_cast<uint4*>(g_A + off) = make_uint4(hv[0], hv[1], hv[2], hv[3]);
    } else if (bx < 3264) {
        // ---- pack B: W [C,H] fp32 -> transposed fp16 [H,C] ----
        int beta = bx - 3072;
        int kc = beta % 12, hb = (beta / 12) & 7, z = beta / 96;
        const float* W = z ? W2 : W1;
        int c0 = kc * 64, h0 = hb * 64;
        #pragma unroll
        for (int i = 0; i < 16; i++) {
            int idx = tid + i * 256;
            int cl = idx >> 6, hl = idx & 63;
            ts[cl][hl] = W[(size_t)(c0 + cl) * H_ + h0 + hl];
        }
        __syncthreads();
        #pragma unroll
        for (int j = 0; j < 2; j++) {
            int unit = tid + j * 256;
            int row = unit >> 3, kg = unit & 7;
            uint32_t hi[4];
            #pragma unroll
            for (int i = 0; i < 4; i++) {
                hi[i] = h2_bits(__float2half_rn(ts[kg * 8 + 2*i][row]),
                                __float2half_rn(ts[kg * 8 + 2*i + 1][row]));
            }
            size_t off = ((size_t)z * 512 + h0 + row) * 768 + c0 + kg * 8;
            *reinterpret_cast<uint4*>(g_B + off) = make_uint4(hi[0], hi[1], hi[2], hi[3]);
        }
    } else {
        // ---- init out with bias * N*N ----
        #pragma unroll
        for (int j = tid; j < B_ * O_; j += 256)
            out[j] = bp[j & (O_ - 1)] * 38416.f;
    }
}

// ---------------- GEMM: single-term fp16 mma.sync + relu + colsum ----------------
// Tile M=64, N=256, BK=64, 256 threads (8 warps: wm{0,1} x wn{0..3}, warp m32 x n64).
// 2-stage ping-pong, ONE __syncthreads per stage (loads issued after the barrier),
// 12 K-stages, 2 CTAs/SM, 256 CTAs = single wave.
#define ROWB 144
#define B_OFF (64*ROWB)                   // A: 64 rows x 144B = 9216
#define STAGE_BYTES (B_OFF + 256*ROWB)    // 46080
#define SMEM_TOTAL (2*STAGE_BYTES)        // 92160

__device__ __forceinline__ void load_stage(
    uint32_t base, int kbase, int tid, const __half* A, const __half* Bp)
{
    #pragma unroll
    for (int i = 0; i < 2; i++) {                 // A: 512 16B units (64 rows x 8 quads)
        int u = tid + i * 256;
        int q = u & 7, row = u >> 3;
        cp16(base + row * ROWB + q * 16, A + (size_t)row * 768 + kbase + q * 8);
    }
    #pragma unroll
    for (int i = 0; i < 8; i++) {                 // B: 2048 16B units (256 rows x 8 quads)
        int u = tid + i * 256;
        int q = u & 7, row = u >> 3;
        cp16(base + B_OFF + row * ROWB + q * 16, Bp + (size_t)row * 768 + kbase + q * 8);
    }
    asm volatile("cp.async.commit_group;" ::: "memory");
}

__global__ __launch_bounds__(256, 2) void gemm_hmma()
{
    extern __shared__ char sm[];
    uint32_t sb = smem_u32(sm);
    int tid = threadIdx.x, wid = tid >> 5, lane = tid & 31;
    int z = blockIdx.z, b = blockIdx.y;
    int mt = blockIdx.x >> 1, nt = blockIdx.x & 1;
    int wm = wid & 1, wn = wid >> 1;

    const __half* A  = g_A + ((size_t)(z * 16 + b) * 256 + mt * 64) * 768;
    const __half* Bp = g_B + ((size_t)z * 512 + nt * 256) * 768;

    float acc[2][8][4];
    #pragma unroll
    for (int mf = 0; mf < 2; mf++)
        #pragma unroll
        for (int nf = 0; nf < 8; nf++)
            #pragma unroll
            for (int d = 0; d < 4; d++) acc[mf][nf][d] = 0.f;

    uint32_t aoff[2];
    #pragma unroll
    for (int mf = 0; mf < 2; mf++) {
        int row = wm * 32 + mf * 16 + (lane & 7) + ((lane >> 3) & 1) * 8;
        aoff[mf] = row * ROWB + (lane >> 4) * 16;
    }
    uint32_t boff[4];
    #pragma unroll
    for (int np = 0; np < 4; np++) {
        int row = wn * 64 + np * 16 + (lane & 7) + (lane >> 4) * 8;
        boff[np] = row * ROWB + ((lane >> 3) & 1) * 16;
    }

    load_stage(sb, 0, tid, A, Bp);

    for (int s = 0; s < 12; s++) {
        asm volatile("cp.async.wait_group 0;" ::: "memory");
        __syncthreads();
        // Issue loads for s+1 AFTER the barrier: the barrier proves all warps
        // finished stage s-1's ldsm reads of buffer (s+1)&1, so overwrite is safe.
        // These cp.asyncs overlap the entire MMA section below.
        if (s < 11)
            load_stage(sb + ((s + 1) & 1) * STAGE_BYTES, (s + 1) * 64, tid, A, Bp);

        uint32_t abase = sb + (s & 1) * STAGE_BYTES;
        uint32_t bbase = abase + B_OFF;
        #pragma unroll
        for (int kk = 0; kk < 4; kk++) {
            uint32_t ah[2][4], bh[4][4];
            #pragma unroll
            for (int mf = 0; mf < 2; mf++)
                ldsm_x4(ah[mf], abase + aoff[mf] + kk * 32);
            #pragma unroll
            for (int np = 0; np < 4; np++)
                ldsm_x4(bh[np], bbase + boff[np] + kk * 32);
            #pragma unroll
            for (int mf = 0; mf < 2; mf++)
                #pragma unroll
                for (int nf = 0; nf < 8; nf++) {
                    int np = nf >> 1, hh = (nf & 1) * 2;
                    uint32_t bb[2] = { bh[np][hh], bh[np][hh + 1] };
                    mma_f32acc(acc[mf][nf], ah[mf], bb);
                }
        }
    }

    // ---------------- epilogue: relu + column sums ----------------
    // red lives in buffer 0 (last read in stage 10; all warps passed the stage-11
    // barrier, so writes are safe without another sync).
    float* red = (float*)sm;     // [2][256] floats
    #pragma unroll
    for (int nf = 0; nf < 8; nf++) {
        float s0 = 0.f, s1 = 0.f;
        #pragma unroll
        for (int mf = 0; mf < 2; mf++) {
            s0 += fmaxf(acc[mf][nf][0], 0.f) + fmaxf(acc[mf][nf][2], 0.f);
            s1 += fmaxf(acc[mf][nf][1], 0.f) + fmaxf(acc[mf][nf][3], 0.f);
        }
        #pragma unroll
        for (int off = 4; off < 32; off <<= 1) {
            s0 += __shfl_xor_sync(0xffffffff, s0, off);
            s1 += __shfl_xor_sync(0xffffffff, s1, off);
        }
        if (lane < 4) {
            red[wm * 256 + wn * 64 + nf * 8 + lane * 2]     = s0;
            red[wm * 256 + wn * 64 + nf * 8 + lane * 2 + 1] = s1;
        }
    }
    __syncthreads();
    float part = red[tid] + red[256 + tid];
    g_part[((size_t)(z * 16 + b) * 4 + mt) * 512 + nt * 256 + tid] = part;
}

// ---------------- finalize: bilinear combine + Wp GEMV (atomic into bias-initialized out) ----------------
__global__ void finalize_acc(const float* __restrict__ Wp, float* __restrict__ out) {
    int b = blockIdx.x, hc = blockIdx.y;   // hc in 0..3, 128 h each
    int tid = threadIdx.x;                 // 128
    __shared__ float sp[128];
    {
        int h = hc * 128 + tid;
        float c1 = 0.f, c2 = 0.f;
        #pragma unroll
        for (int mtq = 0; mtq < 4; mtq++) {
            c1 += g_part[((size_t)(0 * 16 + b) * 4 + mtq) * 512 + h];
            c2 += g_part[((size_t)(1 * 16 + b) * 4 + mtq) * 512 + h];
        }
        sp[tid] = c1 * c2;
    }
    __syncthreads();
    float acc = 0.f;
    #pragma unroll 16
    for (int i = 0; i < 128; i++)
        acc = fmaf(sp[i], Wp[(size_t)(hc * 128 + i) * O_ + tid], acc);
    atomicAdd(&out[b * O_ + tid], acc);
}

// ---------------- launch ----------------
extern "C" void kernel_launch(void* const* d_in, const int* in_sizes, int n_in,
                              void* d_out, int out_size) {
    const float* x1 = (const float*)d_in[0];
    const float* x2 = (const float*)d_in[1];
    const float* W1 = (const float*)d_in[2];
    const float* W2 = (const float*)d_in[3];
    const float* Wp = (const float*)d_in[4];
    const float* bp = (const float*)d_in[5];
    float* out = (float*)d_out;

    cudaFuncSetAttribute(gemm_hmma, cudaFuncAttributeMaxDynamicSharedMemorySize, SMEM_TOTAL);

    pack_all<<<3265, 256>>>(x1, x2, W1, W2, bp, out);
    gemm_hmma<<<dim3(8, 16, 2), 256, SMEM_TOTAL>>>();
    finalize_acc<<<dim3(16, 4), 128>>>(Wp, out);
}